// round 9
// baseline (speedup 1.0000x reference)
#include <cuda_runtime.h>
#include <math.h>

#define BB    16
#define SIN   400
#define SOUT  100
#define HH    256
#define EE    128
#define VV    50000
#define G4    1024
#define H2    512
#define G8    2048
#define NROW  (BB*SOUT)
#define EPSF  1e-10f

typedef unsigned long long ull;

// ---------------- static device scratch ----------------
__device__ float4 g_WtEf4[256*256];     // enc Whh fwd: [k][cell] -> (i,f,g,o)
__device__ float4 g_WtEb4[256*256];
__device__ float4 g_WtD4 [512*512];     // dec Whh
__device__ float4 g_WihTf4[128*256];    // enc Wih fwd: [e][cell]
__device__ float4 g_WihTb4[128*256];
__device__ float4 g_WihTd4[128*512];
__device__ float  g_xgf[BB*SIN*G4];
__device__ float  g_xgb[BB*SIN*G4];
__device__ float  g_xgd[BB*SOUT*G8];
__device__ float  g_ansemb[BB*SOUT*EE];
__device__ float  g_xb[BB*SIN*H2];
__device__ float  g_h0[BB*H2];
__device__ float  g_c0[BB*H2];
__device__ float  g_feat[NROW*G4];      // [row][0:512]=dec_out, [512:1024]=context
__device__ float  g_attn[NROW*SIN];
__device__ float  g_pgen[NROW];
__device__ float  g_rmax[NROW];
__device__ float  g_rscale[NROW];

__device__ __forceinline__ float sigm(float x){ return 1.f/(1.f+__expf(-x)); }
__device__ __forceinline__ float tanh_(float x){ return 2.f/(1.f+__expf(-2.f*x)) - 1.f; }
__device__ __forceinline__ ull dup2(float v){
    unsigned int u = __float_as_uint(v);
    return ((ull)u << 32) | (ull)u;
}
__device__ __forceinline__ void fma2(ull &d, ull a, ull b){
    asm("fma.rn.f32x2 %0, %1, %2, %0;" : "+l"(d) : "l"(a), "l"(b));
}

// ---------------- weight transposes ----------------
__global__ void k_transpose(const float* __restrict__ ef, const float* __restrict__ eb,
                            const float* __restrict__ dw, const float* __restrict__ wif,
                            const float* __restrict__ wib, const float* __restrict__ wid_)
{
    int job = blockIdx.y;
    int idx = blockIdx.x*256 + threadIdx.x;
    if (job == 0) {
        if (idx < 256*256){ int k = idx>>8, j = idx&255;
            g_WtEf4[idx] = make_float4(ef[j*256+k], ef[(256+j)*256+k], ef[(512+j)*256+k], ef[(768+j)*256+k]); }
    } else if (job == 1) {
        if (idx < 256*256){ int k = idx>>8, j = idx&255;
            g_WtEb4[idx] = make_float4(eb[j*256+k], eb[(256+j)*256+k], eb[(512+j)*256+k], eb[(768+j)*256+k]); }
    } else if (job == 2) {
        if (idx < 512*512){ int k = idx>>9, c = idx&511;
            g_WtD4[idx] = make_float4(dw[c*512+k], dw[(512+c)*512+k], dw[(1024+c)*512+k], dw[(1536+c)*512+k]); }
    } else if (job == 3) {
        if (idx < 128*256){ int e = idx>>8, c = idx&255;
            g_WihTf4[idx] = make_float4(wif[c*128+e], wif[(256+c)*128+e], wif[(512+c)*128+e], wif[(768+c)*128+e]); }
    } else if (job == 4) {
        if (idx < 128*256){ int e = idx>>8, c = idx&255;
            g_WihTb4[idx] = make_float4(wib[c*128+e], wib[(256+c)*128+e], wib[(512+c)*128+e], wib[(768+c)*128+e]); }
    } else {
        if (idx < 128*512){ int e = idx>>9, c = idx&511;
            g_WihTd4[idx] = make_float4(wid_[c*128+e], wid_[(512+c)*128+e], wid_[(1024+c)*128+e], wid_[(1536+c)*128+e]); }
    }
}

// ---------------- encoder input gates: xg = emb[x] @ Wih^T + b ----------------
__global__ void k_xg_enc(const int* __restrict__ x, const float* __restrict__ emb,
                         const float* __restrict__ bf, const float* __restrict__ bb)
{
    int dir = blockIdx.z, b = blockIdx.y, t0 = blockIdx.x*8;
    __shared__ float es[8][132];
    int tid = threadIdx.x;
    {
        int i = tid >> 5, v = tid & 31;
        int tt = t0 + i;
        int tsrc = dir ? (SIN-1-tt) : tt;
        int tok = x[b*SIN + tsrc];
        float4 e4 = ((const float4*)emb)[tok*32 + v];
        es[i][v*4+0]=e4.x; es[i][v*4+1]=e4.y; es[i][v*4+2]=e4.z; es[i][v*4+3]=e4.w;
    }
    __syncthreads();
    int cell = tid;
    const float* bias = dir ? bb : bf;
    float acc[8][4];
    #pragma unroll
    for (int i=0;i<8;i++){
        acc[i][0]=bias[cell]; acc[i][1]=bias[256+cell];
        acc[i][2]=bias[512+cell]; acc[i][3]=bias[768+cell];
    }
    const float4* W = dir ? g_WihTb4 : g_WihTf4;
    for (int e=0;e<128;e++){
        float4 w = W[e*256 + cell];
        #pragma unroll
        for (int i=0;i<8;i++){
            float xe = es[i][e];
            acc[i][0] = fmaf(w.x, xe, acc[i][0]);
            acc[i][1] = fmaf(w.y, xe, acc[i][1]);
            acc[i][2] = fmaf(w.z, xe, acc[i][2]);
            acc[i][3] = fmaf(w.w, xe, acc[i][3]);
        }
    }
    float* xg = (dir ? g_xgb : g_xgf) + (size_t)(b*SIN + t0)*G4;
    #pragma unroll
    for (int i=0;i<8;i++){
        #pragma unroll
        for (int q=0;q<4;q++) xg[i*G4 + q*256 + cell] = acc[i][q];
    }
}

// ---------------- decoder input gates + ans embedding ----------------
__global__ void k_xg_dec(const int* __restrict__ ans, const float* __restrict__ emb,
                         const float* __restrict__ db)
{
    int b = blockIdx.y, t0 = blockIdx.x*4;
    __shared__ float es[4][132];
    int tid = threadIdx.x;
    if (tid < 128){
        int i = tid >> 5, v = tid & 31;
        int tt = t0 + i;
        int tok = ans[b*SOUT + tt];
        float4 e4 = ((const float4*)emb)[tok*32 + v];
        es[i][v*4+0]=e4.x; es[i][v*4+1]=e4.y; es[i][v*4+2]=e4.z; es[i][v*4+3]=e4.w;
        ((float4*)g_ansemb)[(b*SOUT+tt)*32 + v] = e4;
    }
    __syncthreads();
    int c = tid;
    float acc0[4][4], acc1[4][4];
    #pragma unroll
    for (int i=0;i<4;i++){
        #pragma unroll
        for (int q=0;q<4;q++){ acc0[i][q] = db[q*512 + c]; acc1[i][q] = db[q*512 + 256 + c]; }
    }
    for (int e=0;e<128;e++){
        float4 w0 = g_WihTd4[e*512 + c];
        float4 w1 = g_WihTd4[e*512 + 256 + c];
        #pragma unroll
        for (int i=0;i<4;i++){
            float xe = es[i][e];
            acc0[i][0]=fmaf(w0.x,xe,acc0[i][0]); acc0[i][1]=fmaf(w0.y,xe,acc0[i][1]);
            acc0[i][2]=fmaf(w0.z,xe,acc0[i][2]); acc0[i][3]=fmaf(w0.w,xe,acc0[i][3]);
            acc1[i][0]=fmaf(w1.x,xe,acc1[i][0]); acc1[i][1]=fmaf(w1.y,xe,acc1[i][1]);
            acc1[i][2]=fmaf(w1.z,xe,acc1[i][2]); acc1[i][3]=fmaf(w1.w,xe,acc1[i][3]);
        }
    }
    #pragma unroll
    for (int i=0;i<4;i++){
        float* xr = g_xgd + (size_t)(b*SOUT + t0 + i)*G8;
        #pragma unroll
        for (int q=0;q<4;q++){ xr[q*512 + c] = acc0[i][q]; xr[q*512 + 256 + c] = acc1[i][q]; }
    }
}

// ---------------- encoder BiLSTM: block owns (dir, b) ----------------
__global__ void __launch_bounds__(256) k_enc()
{
    int dir = blockIdx.x >> 4, b = blockIdx.x & 15;
    const float4* __restrict__ Wt = dir ? g_WtEb4 : g_WtEf4;
    const float* xg = (dir ? g_xgb : g_xgf) + (size_t)b*SIN*G4;
    __shared__ float hs[256];
    int j = threadIdx.x;
    float c = 0.f, hn = 0.f;
    hs[j] = 0.f;
    __syncthreads();
    for (int t=0;t<SIN;t++){
        const float* xr = xg + (size_t)t*G4;
        float gi=xr[j], gf=xr[256+j], gg=xr[512+j], go=xr[768+j];
        #pragma unroll 8
        for (int k=0;k<256;k++){
            float hk = hs[k];
            float4 w = Wt[k*256 + j];
            gi = fmaf(w.x, hk, gi); gf = fmaf(w.y, hk, gf);
            gg = fmaf(w.z, hk, gg); go = fmaf(w.w, hk, go);
        }
        float cn = sigm(gf)*c + sigm(gi)*tanh_(gg);
        hn = sigm(go)*tanh_(cn);
        c = cn;
        __syncthreads();
        hs[j] = hn;
        int tp = dir ? (SIN-1-t) : t;
        g_xb[(size_t)(b*SIN + tp)*H2 + dir*256 + j] = hn;
        __syncthreads();
    }
    g_h0[b*H2 + dir*256 + j] = hn;
    g_c0[b*H2 + dir*256 + j] = c;
}

// ---------------- decoder LSTM (hidden 512) ----------------
__global__ void __launch_bounds__(256) k_dec()
{
    int b = blockIdx.x, j = threadIdx.x;
    __shared__ float hs[512];
    float c0 = g_c0[b*H2 + j], c1 = g_c0[b*H2 + 256 + j];
    hs[j]     = g_h0[b*H2 + j];
    hs[256+j] = g_h0[b*H2 + 256 + j];
    __syncthreads();
    for (int t=0;t<SOUT;t++){
        const float* xr = g_xgd + (size_t)(b*SOUT + t)*G8;
        float ai=xr[j],     af=xr[512+j],  ag=xr[1024+j], ao=xr[1536+j];
        float bi=xr[256+j], bf=xr[768+j],  bg=xr[1280+j], bo=xr[1792+j];
        #pragma unroll 4
        for (int k=0;k<512;k++){
            float hk = hs[k];
            float4 w0 = g_WtD4[k*512 + j];
            float4 w1 = g_WtD4[k*512 + 256 + j];
            ai=fmaf(w0.x,hk,ai); af=fmaf(w0.y,hk,af); ag=fmaf(w0.z,hk,ag); ao=fmaf(w0.w,hk,ao);
            bi=fmaf(w1.x,hk,bi); bf=fmaf(w1.y,hk,bf); bg=fmaf(w1.z,hk,bg); bo=fmaf(w1.w,hk,bo);
        }
        float cn0 = sigm(af)*c0 + sigm(ai)*tanh_(ag);
        float h0n = sigm(ao)*tanh_(cn0);
        float cn1 = sigm(bf)*c1 + sigm(bi)*tanh_(bg);
        float h1n = sigm(bo)*tanh_(cn1);
        c0 = cn0; c1 = cn1;
        __syncthreads();
        hs[j] = h0n; hs[256+j] = h1n;
        float* fr = g_feat + (size_t)(b*SOUT + t)*G4;
        fr[j] = h0n; fr[256+j] = h1n;
        __syncthreads();
    }
}

// ---------------- attention + context + pgen ----------------
__global__ void __launch_bounds__(256) k_attn(const float* __restrict__ wpg, const float* __restrict__ bpg)
{
    int row = blockIdx.x;
    int b = row / SOUT;
    __shared__ float ds[512];
    __shared__ float ctx[512];
    __shared__ float sc[SIN];
    __shared__ float red[256];
    int tid = threadIdx.x, lane = tid & 31, wid = tid >> 5;
    float* feat = g_feat + (size_t)row*G4;
    ds[tid] = feat[tid]; ds[256+tid] = feat[256+tid];
    __syncthreads();

    // scores: warp per source position
    const float4* ds4 = (const float4*)ds;
    for (int s = wid; s < SIN; s += 8){
        const float4* xr = (const float4*)(g_xb + (size_t)(b*SIN + s)*H2);
        float acc = 0.f;
        #pragma unroll
        for (int i=0;i<4;i++){
            float4 a = xr[lane + i*32];
            float4 d = ds4[lane + i*32];
            acc += a.x*d.x + a.y*d.y + a.z*d.z + a.w*d.w;
        }
        #pragma unroll
        for (int o=16;o>0;o>>=1) acc += __shfl_xor_sync(0xffffffffu, acc, o);
        if (lane == 0) sc[s] = acc;
    }
    __syncthreads();

    // softmax over 400
    float m = -1e30f;
    for (int s = tid; s < SIN; s += 256) m = fmaxf(m, sc[s]);
    red[tid] = m; __syncthreads();
    for (int st=128; st>0; st>>=1){ if (tid < st) red[tid] = fmaxf(red[tid], red[tid+st]); __syncthreads(); }
    m = red[0]; __syncthreads();
    float ssum = 0.f;
    for (int s = tid; s < SIN; s += 256) ssum += __expf(sc[s] - m);
    red[tid] = ssum; __syncthreads();
    for (int st=128; st>0; st>>=1){ if (tid < st) red[tid] += red[tid+st]; __syncthreads(); }
    float inv = 1.f / red[0]; __syncthreads();
    for (int s = tid; s < SIN; s += 256){
        float a = __expf(sc[s] - m) * inv;
        sc[s] = a;
        g_attn[(size_t)row*SIN + s] = a;
    }
    __syncthreads();

    // context[d] = sum_s attn[s] * xb[s][d]
    #pragma unroll
    for (int h=0; h<2; h++){
        int d = tid + h*256;
        float acc = 0.f;
        const float* xp = g_xb + (size_t)b*SIN*H2 + d;
        for (int s=0; s<SIN; s++) acc = fmaf(sc[s], xp[(size_t)s*H2], acc);
        ctx[d] = acc;
        feat[512 + d] = acc;
    }
    __syncthreads();

    // pgen = sigmoid(Wpg . [ctx, dec_out, ans_emb] + b)
    float p = 0.f;
    #pragma unroll
    for (int h=0; h<2; h++){
        int i = tid + h*256;
        p += wpg[i]*ctx[i] + wpg[512+i]*ds[i];
    }
    if (tid < 128) p += wpg[1024+tid] * g_ansemb[(size_t)row*EE + tid];
    red[tid] = p; __syncthreads();
    for (int st=128; st>0; st>>=1){ if (tid < st) red[tid] += red[tid+st]; __syncthreads(); }
    if (tid == 0) g_pgen[row] = sigm(red[0] + bpg[0]);
}

// ---------------- projection GEMM: out = feat @ W_pro^T + b_pro (f32x2) ----------------
__global__ void __launch_bounds__(256) k_gemm(const float* __restrict__ Wp,
                                              const float* __restrict__ bp,
                                              float* __restrict__ out)
{
    __shared__ float As[16][128];
    __shared__ ull   Bs2[16][128];
    int m0 = blockIdx.y*128, n0 = blockIdx.x*128;
    int tid = threadIdx.x;
    int tx = tid & 15, ty = tid >> 4;
    int lm = tid >> 2;
    int lk = (tid & 3) * 4;
    ull acc[4][8];
    #pragma unroll
    for (int p=0;p<4;p++)
        #pragma unroll
        for (int j=0;j<8;j++) acc[p][j] = 0ull;

    for (int kt = 0; kt < 64; kt++){
        int kb = kt*16;
        #pragma unroll
        for (int h=0; h<2; h++){
            int r = lm + h*64;
            int gm = m0 + r;
            float4 a4 = make_float4(0.f,0.f,0.f,0.f);
            if (gm < NROW) a4 = *(const float4*)(g_feat + (size_t)gm*G4 + kb + lk);
            As[lk+0][r]=a4.x; As[lk+1][r]=a4.y; As[lk+2][r]=a4.z; As[lk+3][r]=a4.w;
            int gn = n0 + r;
            float4 b4 = make_float4(0.f,0.f,0.f,0.f);
            if (gn < VV) b4 = *(const float4*)(Wp + (size_t)gn*G4 + kb + lk);
            Bs2[lk+0][r]=dup2(b4.x); Bs2[lk+1][r]=dup2(b4.y);
            Bs2[lk+2][r]=dup2(b4.z); Bs2[lk+3][r]=dup2(b4.w);
        }
        __syncthreads();
        #pragma unroll
        for (int k=0;k<16;k++){
            ulonglong2 la0 = *(const ulonglong2*)&As[k][ty*8];
            ulonglong2 la1 = *(const ulonglong2*)&As[k][ty*8+4];
            ulonglong2 lb0 = *(const ulonglong2*)&Bs2[k][tx*8];
            ulonglong2 lb1 = *(const ulonglong2*)&Bs2[k][tx*8+2];
            ulonglong2 lb2 = *(const ulonglong2*)&Bs2[k][tx*8+4];
            ulonglong2 lb3 = *(const ulonglong2*)&Bs2[k][tx*8+6];
            ull av[4] = {la0.x, la0.y, la1.x, la1.y};
            ull bv[8] = {lb0.x, lb0.y, lb1.x, lb1.y, lb2.x, lb2.y, lb3.x, lb3.y};
            #pragma unroll
            for (int j=0;j<8;j++){
                #pragma unroll
                for (int p=0;p<4;p++) fma2(acc[p][j], av[p], bv[j]);
            }
        }
        __syncthreads();
    }
    #pragma unroll
    for (int p=0;p<4;p++){
        int gm = m0 + ty*8 + p*2;
        #pragma unroll
        for (int j=0;j<8;j++){
            int gn = n0 + tx*8 + j;
            if (gn < VV){
                union { ull u; float2 f; } cv; cv.u = acc[p][j];
                float bb = bp[gn];
                if (gm < NROW)     out[(size_t)gm*VV + gn]     = cv.f.x + bb;
                if (gm+1 < NROW)   out[(size_t)(gm+1)*VV + gn] = cv.f.y + bb;
            }
        }
    }
}

// ---------------- row softmax stats ----------------
__global__ void __launch_bounds__(256) k_rowstats(const float* __restrict__ out)
{
    int row = blockIdx.x, tid = threadIdx.x;
    __shared__ float red[256];
    const float* r = out + (size_t)row*VV;
    float m = -1e30f;
    for (int i = tid; i < VV; i += 256) m = fmaxf(m, r[i]);
    red[tid] = m; __syncthreads();
    for (int st=128; st>0; st>>=1){ if (tid < st) red[tid] = fmaxf(red[tid], red[tid+st]); __syncthreads(); }
    m = red[0]; __syncthreads();
    float s = 0.f;
    for (int i = tid; i < VV; i += 256) s += __expf(r[i] - m);
    red[tid] = s; __syncthreads();
    for (int st=128; st>0; st>>=1){ if (tid < st) red[tid] += red[tid+st]; __syncthreads(); }
    if (tid == 0){
        g_rmax[row] = m;
        g_rscale[row] = g_pgen[row] / red[0];
    }
}

// ---------------- transform logits -> pgen*softmax + eps ----------------
__global__ void k_transform(float* __restrict__ out)
{
    int row = blockIdx.y;
    int p = blockIdx.x*256 + threadIdx.x;
    if (p >= VV/4) return;
    float m = g_rmax[row], sc = g_rscale[row];
    float4* o4 = (float4*)(out + (size_t)row*VV);
    float4 v = o4[p];
    v.x = sc*__expf(v.x - m) + EPSF;
    v.y = sc*__expf(v.y - m) + EPSF;
    v.z = sc*__expf(v.z - m) + EPSF;
    v.w = sc*__expf(v.w - m) + EPSF;
    o4[p] = v;
}

// ---------------- pointer scatter ----------------
__global__ void k_scatter(const int* __restrict__ x, float* __restrict__ out)
{
    int row = blockIdx.x, s = threadIdx.x;
    if (s >= SIN) return;
    int b = row / SOUT;
    float w = (1.f - g_pgen[row]) * g_attn[(size_t)row*SIN + s];
    atomicAdd(out + (size_t)row*VV + x[b*SIN + s], w);
}

// ---------------- final log ----------------
__global__ void k_log(float* __restrict__ out)
{
    int row = blockIdx.y;
    int p = blockIdx.x*256 + threadIdx.x;
    if (p >= VV/4) return;
    float4* o4 = (float4*)(out + (size_t)row*VV);
    float4 v = o4[p];
    v.x = logf(v.x); v.y = logf(v.y); v.z = logf(v.z); v.w = logf(v.w);
    o4[p] = v;
}

extern "C" void kernel_launch(void* const* d_in, const int* in_sizes, int n_in,
                              void* d_out, int out_size)
{
    const int*   x    = (const int*)  d_in[0];
    const int*   ans  = (const int*)  d_in[1];
    const float* emb  = (const float*)d_in[2];
    const float* wif  = (const float*)d_in[3];
    const float* ehf  = (const float*)d_in[4];
    const float* ebf  = (const float*)d_in[5];
    const float* wib  = (const float*)d_in[6];
    const float* ehb  = (const float*)d_in[7];
    const float* ebb  = (const float*)d_in[8];
    const float* wid_ = (const float*)d_in[9];
    const float* dwh  = (const float*)d_in[10];
    const float* db   = (const float*)d_in[11];
    const float* Wp   = (const float*)d_in[12];
    const float* bp   = (const float*)d_in[13];
    const float* wpg  = (const float*)d_in[14];
    const float* bpg  = (const float*)d_in[15];
    float* out = (float*)d_out;

    k_transpose<<<dim3(1024,6), 256>>>(ehf, ehb, dwh, wif, wib, wid_);
    k_xg_enc<<<dim3(SIN/8, BB, 2), 256>>>(x, emb, ebf, ebb);
    k_xg_dec<<<dim3(SOUT/4, BB), 256>>>(ans, emb, db);
    k_enc<<<32, 256>>>();
    k_dec<<<BB, 256>>>();
    k_attn<<<NROW, 256>>>(wpg, bpg);
    k_gemm<<<dim3((VV+127)/128, (NROW+127)/128), 256>>>(Wp, bp, out);
    k_rowstats<<<NROW, 256>>>(out);
    k_transform<<<dim3((VV/4+255)/256, NROW), 256>>>(out);
    k_scatter<<<NROW, 512>>>(x, out);
    k_log<<<dim3((VV/4+255)/256, NROW), 256>>>(out);
}